// round 14
// baseline (speedup 1.0000x reference)
#include <cuda_runtime.h>
#include <cuda_bf16.h>
#include <cstdint>

// Kendall's tau loss via discordant-pair count (no ties in random normals):
//   loss = 4*D / (n(n-1)),  D = #{i<j : sign(p_i-p_j) != sign(t_i-t_j)}
// R14 (= R13 + compile fix): bf16x2 pair engine -- 2 pairs (2 rows x 1 j)
// per 5 all-32-bit instrs:
//   sub.rn.bf16x2 (dp0,dp1) + sub.rn.bf16x2 (dt0,dt1)
//   + LOP3 (sp^st)&0x80008000 + SHR 15 + IADD (packed u16-lane accumulate).
// Kills the +2-MOV/pair tax every 64-bit-pair formulation paid (measured
// 5.4 slots/pair vs 3.25 modeled in R12). bf16 comparison flips affect only
// |diff|<~0.004 pairs, net error ~1e2 counts vs 1.7e4 budget (rel_err 1e-3).
// Diagonal tiles stay exact fp32. Shape: proven 528 blocks x 128 threads.

#define TILE 256
#define NTH 128

__device__ unsigned long long g_cnt = 0;  // bits[0:40) count, bits[40:) block ctr

// 2 pairs: rows packed in ap/at (bf16x2), j splatted in bp/bt (bf16x2 of -pj/-tj).
// c accumulates row0 in bits[0:16), row1 in bits[16:32).
__device__ __forceinline__ void acc2(unsigned int& c,
                                     unsigned int ap, unsigned int at,
                                     unsigned int bp, unsigned int bt,
                                     unsigned int mask) {
    asm("{\n\t"
        ".reg .b32 sp, st, x;\n\t"
        "add.rn.bf16x2 sp, %1, %2;\n\t"   // (p_i0-p_j, p_i1-p_j)  [a + (-b)]
        "add.rn.bf16x2 st, %3, %4;\n\t"   // (t_i0-t_j, t_i1-t_j)
        "lop3.b32 x, sp, st, %5, 0x28;\n\t" // (sp ^ st) & 0x80008000
        "shr.u32 x, x, 15;\n\t"             // bits -> 0 and 16
        "add.u32 %0, %0, x;\n\t"
        "}" : "+r"(c) : "r"(ap), "r"(bp), "r"(at), "r"(bt), "r"(mask));
}

__device__ __forceinline__ unsigned int bf2_bits(float lo, float hi) {
    __nv_bfloat162 v = __floats2bfloat162_rn(lo, hi);
    return *reinterpret_cast<unsigned int*>(&v);
}

__global__ __launch_bounds__(NTH) void kt_kernel(
    const float* __restrict__ p, const float* __restrict__ t,
    float* __restrict__ out, int n)
{
    const int ntiles = (n + TILE - 1) / TILE;

    // Linear block id -> upper-triangular (bi, bj), bj >= bi.
    int b = blockIdx.x;
    int bi = 0;
    while (b >= ntiles - bi) { b -= ntiles - bi; ++bi; }
    const int bj = bi + b;

    __shared__ __align__(16) uint2  sb[TILE];   // x: bf16x2(-p_j,-p_j), y: bf16x2(-t_j,-t_j)
    __shared__ __align__(16) float2 sf[TILE];   // raw (p_j, t_j) for exact diagonal path

    const int tid = threadIdx.x;
    const int jb = bj * TILE;
    const int jlim = min(TILE, n - jb);

    #pragma unroll
    for (int k = tid; k < TILE; k += NTH) {
        if (k < jlim) {
            const float pj = p[jb + k];
            const float tj = t[jb + k];
            sb[k] = make_uint2(bf2_bits(-pj, -pj), bf2_bits(-tj, -tj));
            sf[k] = make_float2(pj, tj);
        }
    }
    __syncthreads();

    const int ib = bi * TILE;
    unsigned int cnt = 0;

    const bool full = (jlim == TILE) && (ib + TILE <= n);

    if (full && bi != bj) {
        // Full off-diagonal tile. 2 rows/thread packed in one bf16x2 each.
        const unsigned int ap = bf2_bits(p[ib + tid], p[ib + tid + NTH]);
        const unsigned int at = bf2_bits(t[ib + tid], t[ib + tid + NTH]);
        const unsigned int mask = 0x80008000u;

        unsigned int c0 = 0, c1 = 0;   // two chains, packed u16 lanes each
        const uint4* B4 = reinterpret_cast<const uint4*>(sb);
        #pragma unroll 8
        for (int k2 = 0; k2 < TILE / 2; ++k2) {
            const uint4 bb = B4[k2];   // LDS.128: two j's (bp0,bt0,bp1,bt1)
            acc2(c0, ap, at, bb.x, bb.y, mask);
            acc2(c1, ap, at, bb.z, bb.w, mask);
        }
        const unsigned int c = c0 + c1;              // lanes still separate
        cnt = (c & 0xFFFFu) + (c >> 16);
    } else if (full) {
        // Diagonal tile: exact fp32, local j > local i.
        const float p0 = p[ib + tid      ], t0 = t[ib + tid      ];
        const float p1 = p[ib + tid + NTH], t1 = t[ib + tid + NTH];
        #pragma unroll 4
        for (int k = tid + 1; k < TILE; ++k) {
            const float2 v = sf[k];
            cnt += (__float_as_uint(p0 - v.x) ^ __float_as_uint(t0 - v.y)) >> 31;
        }
        #pragma unroll 4
        for (int k = tid + NTH + 1; k < TILE; ++k) {
            const float2 v = sf[k];
            cnt += (__float_as_uint(p1 - v.x) ^ __float_as_uint(t1 - v.y)) >> 31;
        }
    } else {
        // Partial tile (not hit for n=8192; kept for generality). Exact fp32.
        #pragma unroll
        for (int r = 0; r < 2; ++r) {
            const int i = ib + tid + r * NTH;
            if (i < n) {
                const float pi = p[i], ti = t[i];
                for (int k = 0; k < jlim; ++k) {
                    if (jb + k > i) {
                        const float2 v = sf[k];
                        cnt += (__float_as_uint(pi - v.x) ^
                                __float_as_uint(ti - v.y)) >> 31;
                    }
                }
            }
        }
    }

    // Warp reduction: single REDUX.SUM.
    cnt = __reduce_add_sync(0xFFFFFFFFu, cnt);

    __shared__ unsigned int wsum[NTH / 32];
    if ((tid & 31) == 0) wsum[tid >> 5] = cnt;
    __syncthreads();

    if (tid == 0) {
        unsigned int total = 0;
        #pragma unroll
        for (int w = 0; w < NTH / 32; ++w) total += wsum[w];

        // One atomic: low 40 bits accumulate D, high bits count finished
        // blocks; the same atomic carries both, so no fence is needed.
        const unsigned long long pkt =
            (unsigned long long)total | (1ULL << 40);
        const unsigned long long old = atomicAdd(&g_cnt, pkt);
        if ((old >> 40) == (unsigned long long)(gridDim.x - 1)) {
            const unsigned long long D = (old + pkt) & ((1ULL << 40) - 1ULL);
            const double nn = (double)n;
            out[0] = (float)(4.0 * (double)D / (nn * (nn - 1.0)));
            atomicExch(&g_cnt, 0ULL);   // reset for next graph replay
        }
    }
}

extern "C" void kernel_launch(void* const* d_in, const int* in_sizes, int n_in,
                              void* d_out, int out_size)
{
    const float* predictions = (const float*)d_in[0];
    const float* true_labels = (const float*)d_in[1];
    float* out = (float*)d_out;
    const int n = in_sizes[0];

    const int ntiles = (n + TILE - 1) / TILE;
    const int nblocks = ntiles * (ntiles + 1) / 2;

    kt_kernel<<<nblocks, NTH>>>(predictions, true_labels, out, n);
}

// round 15
// speedup vs baseline: 1.2113x; 1.2113x over previous
#include <cuda_runtime.h>
#include <cuda_bf16.h>
#include <cstdint>

// Kendall's tau loss via discordant-pair count (no ties in random normals):
//   loss = 4*D / (n(n-1)),  D = #{i<j : sign(p_i-p_j) != sign(t_i-t_j)}
// R15: rectangular tiles TI=256 x TJ=128 -> 1056 blocks (7.1/SM, ~28 warps/SM;
// fixes R14's 3.6-blocks/SM wave-tail + low warps/SMSP without R10's 2080-block
// wall penalty). Inner loop tightened to 4 slots / 2 pairs:
//   add.rn.bf16x2 x2 (fma pipe) + LOP3 (a^b)&m (alu) + LEA.HI c+=x>>15 (alu).
// bf16 rounding error measured at rel_err 6.4e-6 in R14 (budget 1e-3).

#define TI 256
#define TJ 128
#define NTH 128

__device__ unsigned long long g_cnt = 0;  // bits[0:40) count, bits[40:) block ctr

// Discord bits for 2 pairs (2 rows x 1 j): returns (dp^dt)&0x80008000.
// Rows packed in ap/at (bf16x2); j splatted in bp/bt (bf16x2 of -pj/-tj).
__device__ __forceinline__ unsigned int disc2(unsigned int ap, unsigned int at,
                                              unsigned int bp, unsigned int bt) {
    unsigned int x;
    asm("{\n\t"
        ".reg .b32 sp, st;\n\t"
        "add.rn.bf16x2 sp, %1, %2;\n\t"      // (p_i0-p_j, p_i1-p_j)
        "add.rn.bf16x2 st, %3, %4;\n\t"      // (t_i0-t_j, t_i1-t_j)
        "lop3.b32 %0, sp, st, 0x80008000, 0x28;\n\t"  // (sp^st)&mask
        "}" : "=r"(x) : "r"(ap), "r"(bp), "r"(at), "r"(bt));
    return x;
}

__device__ __forceinline__ unsigned int bf2_bits(float lo, float hi) {
    __nv_bfloat162 v = __floats2bfloat162_rn(lo, hi);
    return *reinterpret_cast<unsigned int*>(&v);
}

__global__ __launch_bounds__(NTH) void kt_kernel(
    const float* __restrict__ p, const float* __restrict__ t,
    float* __restrict__ out, int n)
{
    const int nti = (n + TI - 1) / TI;        // i-tiles (256 wide)
    const int ntj = (n + TJ - 1) / TJ;        // j-tiles (128 wide)
    const int R = TI / TJ;                    // j-tiles per i-tile (=2)

    // Decode linear block id -> (bi, bj2): i-tile bi, j-tile bj2 >= R*bi.
    int b = blockIdx.x;
    int bi = 0;
    while (b >= ntj - R * bi) { b -= ntj - R * bi; ++bi; }
    const int bj2 = R * bi + b;

    __shared__ __align__(16) uint2  sb[TJ];  // (bf16x2(-pj,-pj), bf16x2(-tj,-tj))
    __shared__ __align__(16) float2 sf[TJ];  // raw (p_j, t_j) for exact overlap path

    const int tid = threadIdx.x;
    const int jb = bj2 * TJ;
    const int jlim = min(TJ, n - jb);

    if (tid < TJ && tid < jlim) {
        const float pj = p[jb + tid];
        const float tj = t[jb + tid];
        sb[tid] = make_uint2(bf2_bits(-pj, -pj), bf2_bits(-tj, -tj));
        sf[tid] = make_float2(pj, tj);
    }
    __syncthreads();

    const int ib = bi * TI;
    unsigned int cnt = 0;

    const bool overlap = (bj2 < R * bi + R);   // j-tile inside this i-tile's range
    const bool full = !overlap && (jlim == TJ) && (ib + TI <= n);

    if (full) {
        // All (i, j) valid: jb >= ib + TI > every i in this tile.
        const unsigned int ap = bf2_bits(p[ib + tid], p[ib + tid + NTH]);
        const unsigned int at = bf2_bits(t[ib + tid], t[ib + tid + NTH]);

        unsigned int c0 = 0, c1 = 0;   // packed u16-lane accumulators
        const uint4* B4 = reinterpret_cast<const uint4*>(sb);
        #pragma unroll 8
        for (int k2 = 0; k2 < TJ / 2; ++k2) {
            const uint4 bb = B4[k2];   // LDS.128: two j's (bp0,bt0,bp1,bt1)
            c0 += disc2(ap, at, bb.x, bb.y) >> 15;   // LEA.HI fuse
            c1 += disc2(ap, at, bb.z, bb.w) >> 15;
        }
        const unsigned int c = c0 + c1;
        cnt = (c & 0xFFFFu) + (c >> 16);
    } else {
        // Overlap or partial: exact fp32 with j > i guard.
        #pragma unroll
        for (int r = 0; r < 2; ++r) {
            const int i = ib + tid + r * NTH;
            if (i < n) {
                const float pi = p[i], ti = t[i];
                for (int k = 0; k < jlim; ++k) {
                    if (jb + k > i) {
                        const float2 v = sf[k];
                        cnt += (__float_as_uint(pi - v.x) ^
                                __float_as_uint(ti - v.y)) >> 31;
                    }
                }
            }
        }
    }

    // Warp reduction: single REDUX.SUM.
    cnt = __reduce_add_sync(0xFFFFFFFFu, cnt);

    __shared__ unsigned int wsum[NTH / 32];
    if ((tid & 31) == 0) wsum[tid >> 5] = cnt;
    __syncthreads();

    if (tid == 0) {
        unsigned int total = 0;
        #pragma unroll
        for (int w = 0; w < NTH / 32; ++w) total += wsum[w];

        // One atomic: low 40 bits accumulate D, high bits count finished
        // blocks; the same atomic carries both, so no fence is needed.
        const unsigned long long pkt =
            (unsigned long long)total | (1ULL << 40);
        const unsigned long long old = atomicAdd(&g_cnt, pkt);
        if ((old >> 40) == (unsigned long long)(gridDim.x - 1)) {
            const unsigned long long D = (old + pkt) & ((1ULL << 40) - 1ULL);
            const double nn = (double)n;
            out[0] = (float)(4.0 * (double)D / (nn * (nn - 1.0)));
            atomicExch(&g_cnt, 0ULL);   // reset for next graph replay
        }
    }
}

extern "C" void kernel_launch(void* const* d_in, const int* in_sizes, int n_in,
                              void* d_out, int out_size)
{
    const float* predictions = (const float*)d_in[0];
    const float* true_labels = (const float*)d_in[1];
    float* out = (float*)d_out;
    const int n = in_sizes[0];

    const int nti = (n + TI - 1) / TI;
    const int ntj = (n + TJ - 1) / TJ;
    const int R = TI / TJ;

    int nblocks = 0;
    for (int bi = 0; bi < nti; ++bi) {
        int c = ntj - R * bi;
        if (c > 0) nblocks += c;
    }

    kt_kernel<<<nblocks, NTH>>>(predictions, true_labels, out, n);
}